// round 1
// baseline (speedup 1.0000x reference)
#include <cuda_runtime.h>
#include <math.h>

#define DM 96
#define DI 192
#define DSN 16
#define RK 6
#define BB 2
#define LL 4096
#define CC 192
#define LT 4288
#define NC 32
#define CL 134

// ---------------- static scratch (no allocs allowed) ----------------
__device__ float  g_wtA[DM * 2 * DI];        // in_proj_w transposed: [k][j] 96x384
__device__ float  g_wtO[DI * DM];            // out_proj_w transposed: [d][o] 192x96
__device__ float  g_An [DI * DSN];           // -exp(A_logs)
__device__ float  g_x1 [BB * DI * LL];       // conv input  (b,c,h,w)
__device__ float  g_xs [BB * DI * LT];       // u = xs      (b,d,ltot): [0,CC)=depth, [CC,LT)=conv out
__device__ float  g_z  [BB * LL * DI];       // z           (b,l,d)
__device__ float  g_dxc[BB * DI * 1024];     // stride-2 conv out (b,c,1024)
__device__ float2 g_bc [BB * LT * DSN];      // (B_n, C_n)  (b,l,n)
__device__ float4 g_quad[BB * DI * LT];      // (delta*log2e, delta*u, Ds*u, 0)
__device__ float  g_yt [BB * LL * DI];       // scan y (+Ds*u) (b,l,d)
__device__ float  g_hend[BB * DI * NC * DSN];
__device__ float  g_P   [BB * DI * NC * DSN];
__device__ float  g_h0  [BB * DI * NC * DSN];

__device__ __forceinline__ float ex2(float x) {
    float r; asm("ex2.approx.ftz.f32 %0, %1;" : "=f"(r) : "f"(x)); return r;
}
__device__ __forceinline__ float silu_f(float v) {
    return __fdividef(v, 1.f + __expf(-v));
}

// ---------------- K0: weight transposes + A table ----------------
__global__ void k0_prep(const float* __restrict__ ipw, const float* __restrict__ opw,
                        const float* __restrict__ alogs) {
    int t = blockIdx.x * blockDim.x + threadIdx.x;
    if (t < 2 * DI * DM) {           // in_proj_w (384,96) -> [k][j]
        int j = t / DM, k = t % DM;
        g_wtA[k * (2 * DI) + j] = ipw[t];
    }
    if (t < DM * DI) {               // out_proj_w (96,192) -> [d][o]
        int o = t / DI, d = t % DI;
        g_wtO[d * DM + o] = opw[t];
    }
    if (t < DI * DSN) {
        g_An[t] = -expf(alogs[t]);
    }
}

// ---------------- K1: xz = x @ in_proj_w.T ; split x1 (NCHW) / z (b,l,d) ----------------
__global__ void __launch_bounds__(384) k1_inproj(const float* __restrict__ x) {
    __shared__ float xt[96 * 36];        // [k][l] padded
    __shared__ float zs[32 * DI];
    int b  = blockIdx.y;
    int l0 = blockIdx.x * 32;
    int tid = threadIdx.x;               // 384

    const float4* xin = (const float4*)(x + ((size_t)b * LL + l0) * DM);
    for (int i = tid; i < 32 * 24; i += 384) {
        float4 v = xin[i];
        int l = i / 24, k4 = (i % 24) * 4;
        xt[(k4 + 0) * 36 + l] = v.x;
        xt[(k4 + 1) * 36 + l] = v.y;
        xt[(k4 + 2) * 36 + l] = v.z;
        xt[(k4 + 3) * 36 + l] = v.w;
    }
    __syncthreads();

    int j = tid;
    float acc[32];
#pragma unroll
    for (int l = 0; l < 32; l++) acc[l] = 0.f;
    for (int k = 0; k < 96; k++) {
        float w = g_wtA[k * 384 + j];
#pragma unroll
        for (int l4 = 0; l4 < 8; l4++) {
            float4 xv = *(const float4*)&xt[k * 36 + l4 * 4];
            acc[l4 * 4 + 0] += xv.x * w;
            acc[l4 * 4 + 1] += xv.y * w;
            acc[l4 * 4 + 2] += xv.z * w;
            acc[l4 * 4 + 3] += xv.w * w;
        }
    }
    if (j < DI) {
        float* dst = g_x1 + ((size_t)b * DI + j) * LL + l0;
#pragma unroll
        for (int l4 = 0; l4 < 8; l4++) {
            *(float4*)(dst + l4 * 4) =
                make_float4(acc[l4*4], acc[l4*4+1], acc[l4*4+2], acc[l4*4+3]);
        }
    } else {
        int d = j - DI;
#pragma unroll
        for (int l = 0; l < 32; l++) zs[l * DI + d] = acc[l];
    }
    __syncthreads();
    float4* zdst = (float4*)(g_z + ((size_t)b * LL + l0) * DI);
    const float4* zsrc = (const float4*)zs;
    for (int i = tid; i < 32 * 48; i += 384) zdst[i] = zsrc[i];
}

// ---------------- K2: depthwise 3x3 s1 p1 + bias + SiLU -> g_xs[CC..] ----------------
__global__ void k2_conv(const float* __restrict__ cw, const float* __restrict__ cb) {
    int plane = blockIdx.y;              // b*192 + c
    int c = plane % DI;
    int tid = threadIdx.x;               // 256
    __shared__ float w[9];
    __shared__ float bias;
    if (tid < 9) w[tid] = cw[c * 9 + tid];
    if (tid == 9) bias = cb[c];
    __syncthreads();
    int h = blockIdx.x * 4 + tid / 64;
    int wx = tid % 64;
    const float* in = g_x1 + (size_t)plane * LL;
    float s = bias;
#pragma unroll
    for (int kh = 0; kh < 3; kh++) {
        int ih = h + kh - 1;
        if (ih < 0 || ih >= 64) continue;
#pragma unroll
        for (int kw = 0; kw < 3; kw++) {
            int iw = wx + kw - 1;
            if (iw < 0 || iw >= 64) continue;
            s += w[kh * 3 + kw] * in[ih * 64 + iw];
        }
    }
    g_xs[(size_t)plane * LT + CC + h * 64 + wx] = silu_f(s);
}

// ---------------- K3: depthwise 3x3 s2 p1 + bias -> g_dxc ----------------
__global__ void k3_dconv(const float* __restrict__ cw, const float* __restrict__ cb) {
    int plane = blockIdx.y;
    int c = plane % DI;
    int tid = threadIdx.x;
    __shared__ float w[9];
    __shared__ float bias;
    if (tid < 9) w[tid] = cw[c * 9 + tid];
    if (tid == 9) bias = cb[c];
    __syncthreads();
    int o  = blockIdx.x * 256 + tid;     // 0..1023
    int oh = o / 32, ow = o % 32;
    const float* in = g_xs + (size_t)plane * LT + CC;
    float s = bias;
#pragma unroll
    for (int kh = 0; kh < 3; kh++) {
        int ih = 2 * oh + kh - 1;
        if (ih < 0 || ih >= 64) continue;
#pragma unroll
        for (int kw = 0; kw < 3; kw++) {
            int iw = 2 * ow + kw - 1;
            if (iw < 0 || iw >= 64) continue;
            s += w[kh * 3 + kw] * in[ih * 64 + iw];
        }
    }
    g_dxc[(size_t)plane * 1024 + o] = s;
}

// ---------------- K4: depth_fc + bias + SiLU -> g_xs[0..CC) ----------------
__global__ void __launch_bounds__(192) k4_fc(const float* __restrict__ wfc,
                                             const float* __restrict__ fcb) {
    __shared__ float xrow[8 * 1024];     // 32 KB
    int b   = blockIdx.y;
    int lp0 = blockIdx.x * 8;
    int tid = threadIdx.x;               // 192
    for (int i = tid; i < 2048; i += 192) {
        int r = i >> 8, k4 = i & 255;
        ((float4*)xrow)[r * 256 + k4] =
            *((const float4*)(g_dxc + ((size_t)b * DI + lp0 + r) * 1024) + k4);
    }
    __syncthreads();
    int d = tid;
    float acc[8];
#pragma unroll
    for (int r = 0; r < 8; r++) acc[r] = 0.f;
    const float4* wr = (const float4*)(wfc + (size_t)d * 1024);
    for (int k4 = 0; k4 < 256; k4++) {
        float4 wv = wr[k4];
#pragma unroll
        for (int r = 0; r < 8; r++) {
            float4 xv = ((float4*)xrow)[r * 256 + k4];
            acc[r] += xv.x * wv.x + xv.y * wv.y + xv.z * wv.z + xv.w * wv.w;
        }
    }
    float bv = fcb[d];
#pragma unroll
    for (int r = 0; r < 8; r++) {
        float v = acc[r] + bv;
        g_xs[((size_t)b * DI + d) * LT + (lp0 + r)] = silu_f(v);
    }
}

// ---------------- K5: x_proj + dt proj + softplus precompute -> g_bc, g_quad ----------------
__global__ void __launch_bounds__(128) k5_xproj(const float* __restrict__ xpw,
                                                const float* __restrict__ dtw,
                                                const float* __restrict__ dtb,
                                                const float* __restrict__ dsv) {
    __shared__ float s_xp[38 * DI];
    __shared__ float s_dtw[DI * RK];
    __shared__ float s_dtb[DI];
    __shared__ float s_ds[DI];
    int tid = threadIdx.x;
    for (int i = tid; i < 38 * DI; i += 128) s_xp[i] = xpw[i];
    for (int i = tid; i < DI * RK; i += 128) s_dtw[i] = dtw[i];
    for (int i = tid; i < DI; i += 128) { s_dtb[i] = dtb[i]; s_ds[i] = dsv[i]; }
    __syncthreads();

    int b = blockIdx.y;
    int l = blockIdx.x * 128 + tid;
    if (l >= LT) return;

    float xd[38];
#pragma unroll
    for (int c = 0; c < 38; c++) xd[c] = 0.f;
    const float* u = g_xs + (size_t)b * DI * LT + l;
    for (int d = 0; d < DI; d++) {
        float xv = u[(size_t)d * LT];
#pragma unroll
        for (int c = 0; c < 38; c++) xd[c] += xv * s_xp[c * DI + d];
    }
    float2* bc = g_bc + ((size_t)b * LT + l) * DSN;
#pragma unroll
    for (int n = 0; n < DSN; n++) bc[n] = make_float2(xd[RK + n], xd[RK + DSN + n]);

    const float L2E = 1.4426950408889634f;
    for (int d = 0; d < DI; d++) {
        float dt = s_dtb[d];
#pragma unroll
        for (int r = 0; r < RK; r++) dt += xd[r] * s_dtw[d * RK + r];
        // softplus, accurate (log1pf keeps small-delta relative error tiny)
        float delta;
        if (dt > 20.f)       delta = dt;
        else if (dt < -20.f) delta = __expf(dt);
        else                 delta = log1pf(__expf(dt));
        float uv = u[(size_t)d * LT];
        g_quad[((size_t)b * DI + d) * LT + l] =
            make_float4(delta * L2E, delta * uv, s_ds[d] * uv, 0.f);
    }
}

// ---------------- K6: chunked selective scan ----------------
__global__ void __launch_bounds__(128) k6_phaseA() {
    int W    = blockIdx.x * 4 + (threadIdx.x >> 5);
    int lane = threadIdx.x & 31;
    int c = W / 192;                 // chunk
    int p = W % 192;                 // pair
    int half = lane >> 4;
    int n = lane & 15;
    int g = 2 * p + half;            // b*DI + d
    int d = g % DI;
    int b = g / DI;
    float An = g_An[d * DSN + n];
    const float4* q  = g_quad + (size_t)g * LT;
    const float2* bc = g_bc + (size_t)b * LT * DSN;
    float h = 0.f, P = 1.f;
    int l0 = c * CL;
#pragma unroll 4
    for (int l = l0; l < l0 + CL; l++) {
        float4 qq = q[l];
        float2 bv = bc[(size_t)l * DSN + n];
        float a = ex2(qq.x * An);
        P *= a;
        h = a * h + qq.y * bv.x;
    }
    int idx = (g * NC + c) * DSN + n;
    g_hend[idx] = h;
    g_P[idx]    = P;
}

__global__ void k6_phaseB() {
    int t = blockIdx.x * blockDim.x + threadIdx.x;   // 6144
    if (t >= BB * DI * DSN) return;
    int n = t & 15;
    int g = t >> 4;
    float h = 0.f;
    for (int c = 0; c < NC; c++) {
        int idx = (g * NC + c) * DSN + n;
        g_h0[idx] = h;
        h = g_P[idx] * h + g_hend[idx];
    }
}

__global__ void __launch_bounds__(128) k6_phaseC() {
    int W    = blockIdx.x * 4 + (threadIdx.x >> 5);
    int lane = threadIdx.x & 31;
    int c = W / 192;
    int p = W % 192;
    int half = lane >> 4;
    int n = lane & 15;
    int g = 2 * p + half;
    int d = g % DI;
    int b = g / DI;
    float An = g_An[d * DSN + n];
    const float4* q  = g_quad + (size_t)g * LT;
    const float2* bc = g_bc + (size_t)b * LT * DSN;
    float h = g_h0[(g * NC + c) * DSN + n];
    int l0 = c * CL;
#pragma unroll 2
    for (int l = l0; l < l0 + CL; l++) {
        float4 qq = q[l];
        float2 bv = bc[(size_t)l * DSN + n];
        float a = ex2(qq.x * An);
        h = a * h + qq.y * bv.x;
        float pr = h * bv.y;
        pr += __shfl_xor_sync(0xffffffffu, pr, 1);
        pr += __shfl_xor_sync(0xffffffffu, pr, 2);
        pr += __shfl_xor_sync(0xffffffffu, pr, 4);
        pr += __shfl_xor_sync(0xffffffffu, pr, 8);
        if (n == 0 && l >= CC) {
            g_yt[((size_t)b * LL + (l - CC)) * DI + d] = pr + qq.z;
        }
    }
}

// ---------------- K7: LayerNorm + SiLU(z) gate + out_proj ----------------
__global__ void __launch_bounds__(192) k7_out(const float* __restrict__ onw,
                                              const float* __restrict__ onb,
                                              float* __restrict__ out) {
    __shared__ float sm[DI];
    __shared__ float red[16];
    __shared__ float acc2[DM];
    int b = blockIdx.y;
    int l = blockIdx.x;
    int tid = threadIdx.x;               // 192
    float y = g_yt[((size_t)b * LL + l) * DI + tid];
    float s1 = y, s2 = y * y;
#pragma unroll
    for (int o = 16; o > 0; o >>= 1) {
        s1 += __shfl_xor_sync(0xffffffffu, s1, o);
        s2 += __shfl_xor_sync(0xffffffffu, s2, o);
    }
    int wid = tid >> 5;
    if ((tid & 31) == 0) { red[wid] = s1; red[8 + wid] = s2; }
    __syncthreads();
    if (tid == 0) {
        float a = 0.f, q = 0.f;
        for (int i = 0; i < 6; i++) { a += red[i]; q += red[8 + i]; }
        float mu  = a * (1.f / 192.f);
        float var = q * (1.f / 192.f) - mu * mu;
        red[14] = mu;
        red[15] = rsqrtf(var + 1e-5f);
    }
    __syncthreads();
    float mu = red[14], rs = red[15];
    float yn = (y - mu) * rs * onw[tid] + onb[tid];
    float zv = g_z[((size_t)b * LL + l) * DI + tid];
    sm[tid] = yn * silu_f(zv);
    __syncthreads();

    int o = tid % DM, part = tid / DM;
    float acc = 0.f;
    int d0 = part * 96;
#pragma unroll 4
    for (int i = 0; i < 96; i++) {
        acc += sm[d0 + i] * g_wtO[(d0 + i) * DM + o];
    }
    if (part == 0) acc2[o] = acc;
    __syncthreads();
    if (part == 1) out[((size_t)b * LL + l) * DM + o] = acc + acc2[o];
}

// ---------------- launch ----------------
extern "C" void kernel_launch(void* const* d_in, const int* in_sizes, int n_in,
                              void* d_out, int out_size) {
    const float* x            = (const float*)d_in[0];
    const float* in_proj_w    = (const float*)d_in[1];
    const float* conv2d_w     = (const float*)d_in[2];
    const float* conv2d_b     = (const float*)d_in[3];
    const float* depth_conv_w = (const float*)d_in[4];
    const float* depth_conv_b = (const float*)d_in[5];
    const float* depth_fc_w   = (const float*)d_in[6];
    const float* depth_fc_b   = (const float*)d_in[7];
    const float* x_proj_w     = (const float*)d_in[8];
    const float* dt_projs_w   = (const float*)d_in[9];
    const float* dt_projs_b   = (const float*)d_in[10];
    const float* A_logs       = (const float*)d_in[11];
    const float* Ds           = (const float*)d_in[12];
    const float* out_norm_w   = (const float*)d_in[13];
    const float* out_norm_b   = (const float*)d_in[14];
    const float* out_proj_w   = (const float*)d_in[15];
    float* out = (float*)d_out;

    k0_prep<<<(2 * DI * DM + 255) / 256, 256>>>(in_proj_w, out_proj_w, A_logs);
    k1_inproj<<<dim3(LL / 32, BB), 384>>>(x);
    k2_conv<<<dim3(16, BB * DI), 256>>>(conv2d_w, conv2d_b);
    k3_dconv<<<dim3(4, BB * DI), 256>>>(depth_conv_w, depth_conv_b);
    k4_fc<<<dim3(24, BB), 192>>>(depth_fc_w, depth_fc_b);
    k5_xproj<<<dim3((LT + 127) / 128, BB), 128>>>(x_proj_w, dt_projs_w, dt_projs_b, Ds);
    k6_phaseA<<<(192 * NC) / 4, 128>>>();
    k6_phaseB<<<24, 256>>>();
    k6_phaseC<<<(192 * NC) / 4, 128>>>();
    k7_out<<<dim3(LL, BB), 192>>>(out_norm_w, out_norm_b, out);
}

// round 3
// speedup vs baseline: 1.4583x; 1.4583x over previous
#include <cuda_runtime.h>
#include <math.h>

#define DM 96
#define DI 192
#define DSN 16
#define RK 6
#define BB 2
#define LL 4096
#define CC 192
#define LT 4288
#define NC 32
#define CL 134

// ---------------- static scratch (no allocs allowed) ----------------
// __align__(16) is mandatory on anything accessed via float4* casts.
__device__ __align__(16) float  g_wtA[DM * 2 * DI];   // in_proj_w transposed: [k][j] 96x384
__device__ __align__(16) float  g_wtO[DI * DM];       // out_proj_w transposed: [d][o] 192x96
__device__ __align__(16) float  g_An [DI * DSN];      // -exp(A_logs)
__device__ __align__(16) float  g_x1 [BB * DI * LL];  // conv input  (b,c,h,w)
__device__ __align__(16) float  g_xs [BB * DI * LT];  // u = xs      (b,d,ltot)
__device__ __align__(16) float  g_z  [BB * LL * DI];  // z           (b,l,d)
__device__ __align__(16) float  g_dxc[BB * DI * 1024];// stride-2 conv out (b,c,1024)
__device__ __align__(16) float2 g_bc [BB * LT * DSN]; // (B_n, C_n)  (b,l,n)
__device__ __align__(16) float2 g_q2 [BB * DI * LT];  // (delta*log2e, delta*u)
__device__ __align__(16) float  g_yt [BB * LL * DI];  // scan y (b,l,d)
__device__ __align__(16) float  g_hend[BB * DI * NC * DSN];
__device__ __align__(16) float  g_P   [BB * DI * NC * DSN];
__device__ __align__(16) float  g_h0  [BB * DI * NC * DSN];

__device__ __forceinline__ float ex2(float x) {
    float r; asm("ex2.approx.ftz.f32 %0, %1;" : "=f"(r) : "f"(x)); return r;
}
__device__ __forceinline__ float silu_f(float v) {
    return __fdividef(v, 1.f + __expf(-v));
}

// ---------------- K0: weight transposes + A table ----------------
__global__ void k0_prep(const float* __restrict__ ipw, const float* __restrict__ opw,
                        const float* __restrict__ alogs) {
    int t = blockIdx.x * blockDim.x + threadIdx.x;
    if (t < 2 * DI * DM) {
        int j = t / DM, k = t % DM;
        g_wtA[k * (2 * DI) + j] = ipw[t];
    }
    if (t < DM * DI) {
        int o = t / DI, d = t % DI;
        g_wtO[d * DM + o] = opw[t];
    }
    if (t < DI * DSN) {
        g_An[t] = -expf(alogs[t]);
    }
}

// ---------------- K1: xz = x @ in_proj_w.T ; split x1 (NCHW) / z (b,l,d) ----------------
__global__ void __launch_bounds__(384) k1_inproj(const float* __restrict__ x) {
    __shared__ __align__(16) float xt[96 * 36];
    __shared__ __align__(16) float zs[32 * DI];
    int b  = blockIdx.y;
    int l0 = blockIdx.x * 32;
    int tid = threadIdx.x;

    const float4* xin = (const float4*)(x + ((size_t)b * LL + l0) * DM);
    for (int i = tid; i < 32 * 24; i += 384) {
        float4 v = xin[i];
        int l = i / 24, k4 = (i % 24) * 4;
        xt[(k4 + 0) * 36 + l] = v.x;
        xt[(k4 + 1) * 36 + l] = v.y;
        xt[(k4 + 2) * 36 + l] = v.z;
        xt[(k4 + 3) * 36 + l] = v.w;
    }
    __syncthreads();

    int j = tid;
    float acc[32];
#pragma unroll
    for (int l = 0; l < 32; l++) acc[l] = 0.f;
    for (int k = 0; k < 96; k++) {
        float w = g_wtA[k * 384 + j];
#pragma unroll
        for (int l4 = 0; l4 < 8; l4++) {
            float4 xv = *(const float4*)&xt[k * 36 + l4 * 4];
            acc[l4 * 4 + 0] += xv.x * w;
            acc[l4 * 4 + 1] += xv.y * w;
            acc[l4 * 4 + 2] += xv.z * w;
            acc[l4 * 4 + 3] += xv.w * w;
        }
    }
    if (j < DI) {
        float* dst = g_x1 + ((size_t)b * DI + j) * LL + l0;
#pragma unroll
        for (int l4 = 0; l4 < 8; l4++) {
            *(float4*)(dst + l4 * 4) =
                make_float4(acc[l4*4], acc[l4*4+1], acc[l4*4+2], acc[l4*4+3]);
        }
    } else {
        int d = j - DI;
#pragma unroll
        for (int l = 0; l < 32; l++) zs[l * DI + d] = acc[l];
    }
    __syncthreads();
    float4* zdst = (float4*)(g_z + ((size_t)b * LL + l0) * DI);
    const float4* zsrc = (const float4*)zs;
    for (int i = tid; i < 32 * 48; i += 384) zdst[i] = zsrc[i];
}

// ---------------- K2: depthwise 3x3 s1 p1 + bias + SiLU -> g_xs[CC..] ----------------
__global__ void k2_conv(const float* __restrict__ cw, const float* __restrict__ cb) {
    int plane = blockIdx.y;
    int c = plane % DI;
    int tid = threadIdx.x;
    __shared__ float w[9];
    __shared__ float bias;
    if (tid < 9) w[tid] = cw[c * 9 + tid];
    if (tid == 9) bias = cb[c];
    __syncthreads();
    int h = blockIdx.x * 4 + tid / 64;
    int wx = tid % 64;
    const float* in = g_x1 + (size_t)plane * LL;
    float s = bias;
#pragma unroll
    for (int kh = 0; kh < 3; kh++) {
        int ih = h + kh - 1;
        if (ih < 0 || ih >= 64) continue;
#pragma unroll
        for (int kw = 0; kw < 3; kw++) {
            int iw = wx + kw - 1;
            if (iw < 0 || iw >= 64) continue;
            s += w[kh * 3 + kw] * in[ih * 64 + iw];
        }
    }
    g_xs[(size_t)plane * LT + CC + h * 64 + wx] = silu_f(s);
}

// ---------------- K3: depthwise 3x3 s2 p1 + bias -> g_dxc ----------------
__global__ void k3_dconv(const float* __restrict__ cw, const float* __restrict__ cb) {
    int plane = blockIdx.y;
    int c = plane % DI;
    int tid = threadIdx.x;
    __shared__ float w[9];
    __shared__ float bias;
    if (tid < 9) w[tid] = cw[c * 9 + tid];
    if (tid == 9) bias = cb[c];
    __syncthreads();
    int o  = blockIdx.x * 256 + tid;
    int oh = o / 32, ow = o % 32;
    const float* in = g_xs + (size_t)plane * LT + CC;
    float s = bias;
#pragma unroll
    for (int kh = 0; kh < 3; kh++) {
        int ih = 2 * oh + kh - 1;
        if (ih < 0 || ih >= 64) continue;
#pragma unroll
        for (int kw = 0; kw < 3; kw++) {
            int iw = 2 * ow + kw - 1;
            if (iw < 0 || iw >= 64) continue;
            s += w[kh * 3 + kw] * in[ih * 64 + iw];
        }
    }
    g_dxc[(size_t)plane * 1024 + o] = s;
}

// ---------------- K4: depth_fc + bias + SiLU (tiled, K-split, coalesced) ----------------
__global__ void __launch_bounds__(384) k4_fc(const float* __restrict__ wfc,
                                             const float* __restrict__ fcb) {
    __shared__ __align__(16) float sW[2][192 * 20]; // padded stride 20
    __shared__ __align__(16) float sX[2][8 * 16];
    __shared__ __align__(16) float sred[192 * 8];
    int b   = blockIdx.y;
    int lp0 = blockIdx.x * 8;
    int tid = threadIdx.x;
    int d   = tid % 192;
    int kh  = tid / 192;                 // K half: 0 -> [0,512), 1 -> [512,1024)

    float acc[8];
#pragma unroll
    for (int r = 0; r < 8; r++) acc[r] = 0.f;

    for (int ch = 0; ch < 32; ch++) {
        int k0 = kh * 512 + ch * 16;
        __syncthreads();
#pragma unroll
        for (int j = 0; j < 4; j++) {
            int q = d + 192 * j;
            int row = q >> 2, col = q & 3;
            float4 v = *(const float4*)(wfc + (size_t)row * 1024 + k0 + col * 4);
            *(float4*)&sW[kh][row * 20 + col * 4] = v;
        }
        if (d < 32) {
            int row = d >> 2, col = d & 3;
            float4 v = *(const float4*)(g_dxc + ((size_t)b * DI + lp0 + row) * 1024 + k0 + col * 4);
            *(float4*)&sX[kh][row * 16 + col * 4] = v;
        }
        __syncthreads();
#pragma unroll
        for (int j4 = 0; j4 < 4; j4++) {
            float4 wv = *(const float4*)&sW[kh][d * 20 + j4 * 4];
#pragma unroll
            for (int r = 0; r < 8; r++) {
                float4 xv = *(const float4*)&sX[kh][r * 16 + j4 * 4];
                acc[r] += wv.x * xv.x + wv.y * xv.y + wv.z * xv.z + wv.w * xv.w;
            }
        }
    }
    __syncthreads();
    if (kh == 0) {
#pragma unroll
        for (int r = 0; r < 8; r++) sred[d * 8 + r] = acc[r];
    }
    __syncthreads();
    if (kh == 1) {
        float bv = fcb[d];
        float o[8];
#pragma unroll
        for (int r = 0; r < 8; r++) o[r] = silu_f(acc[r] + sred[d * 8 + r] + bv);
        float* dst = g_xs + ((size_t)b * DI + d) * LT + lp0;
        *(float4*)dst       = make_float4(o[0], o[1], o[2], o[3]);
        *(float4*)(dst + 4) = make_float4(o[4], o[5], o[6], o[7]);
    }
}

// ---------------- K5: x_proj + dt proj + softplus precompute (tiled) ----------------
__global__ void __launch_bounds__(256) k5_xproj(const float* __restrict__ xpw,
                                                const float* __restrict__ dtw,
                                                const float* __restrict__ dtb,
                                                const float* __restrict__ dsv) {
    __shared__ __align__(16) float s_xp[38 * 193];   // padded
    __shared__ __align__(16) float sxd[38 * 36];     // xd[c][l], padded stride 36
    __shared__ __align__(16) float s_dtw[DI * RK];
    __shared__ float s_dtb[DI];
    __shared__ float s_ds[DI];
    int tid = threadIdx.x;
    int b   = blockIdx.y;
    int l0  = blockIdx.x * 32;

    for (int i = tid; i < 38 * DI; i += 256) s_xp[(i / DI) * 193 + (i % DI)] = xpw[i];
    for (int i = tid; i < DI * RK; i += 256) s_dtw[i] = dtw[i];
    for (int i = tid; i < DI; i += 256) { s_dtb[i] = dtb[i]; s_ds[i] = dsv[i]; }
    __syncthreads();

    const float* ub = g_xs + (size_t)b * DI * LT + l0;
    // stage 1: xd[c][l] = sum_d u[d][l] * xp[c][d]; item = c*8 + lq
    for (int item = tid; item < 38 * 8; item += 256) {
        int c = item >> 3, lq = item & 7;
        float4 acc = make_float4(0.f, 0.f, 0.f, 0.f);
        const float* xr = s_xp + c * 193;
#pragma unroll 4
        for (int d = 0; d < DI; d++) {
            float xp = xr[d];
            float4 uv = *(const float4*)(ub + (size_t)d * LT + lq * 4);
            acc.x += xp * uv.x; acc.y += xp * uv.y;
            acc.z += xp * uv.z; acc.w += xp * uv.w;
        }
        *(float4*)&sxd[c * 36 + lq * 4] = acc;
    }
    __syncthreads();

    // bc store: coalesced (l,n) layout
    {
        int n = tid & 15;
        int lh = tid >> 4;               // 0..15
#pragma unroll
        for (int rr = 0; rr < 2; rr++) {
            int l = lh + rr * 16;
            g_bc[((size_t)b * LT + l0 + l) * DSN + n] =
                make_float2(sxd[(RK + n) * 36 + l], sxd[(RK + DSN + n) * 36 + l]);
        }
    }

    // stage 2: dts -> softplus -> q2; item = d*8 + lq
    const float L2E = 1.4426950408889634f;
    for (int item = tid; item < DI * 8; item += 256) {
        int d = item >> 3, lq = item & 7;
        float dt0 = s_dtb[d], dt1 = dt0, dt2 = dt0, dt3 = dt0;
#pragma unroll
        for (int r = 0; r < RK; r++) {
            float w = s_dtw[d * RK + r];
            float4 xv = *(const float4*)&sxd[r * 36 + lq * 4];
            dt0 += w * xv.x; dt1 += w * xv.y; dt2 += w * xv.z; dt3 += w * xv.w;
        }
        float del[4]; float dts[4] = {dt0, dt1, dt2, dt3};
#pragma unroll
        for (int j = 0; j < 4; j++) {
            float dt = dts[j];
            if (dt > 20.f)       del[j] = dt;
            else if (dt < -20.f) del[j] = __expf(dt);
            else                 del[j] = log1pf(__expf(dt));
        }
        float4 uv = *(const float4*)(ub + (size_t)d * LT + lq * 4);
        float2* qd = g_q2 + ((size_t)b * DI + d) * LT + l0 + lq * 4;
        *(float4*)qd       = make_float4(del[0] * L2E, del[0] * uv.x, del[1] * L2E, del[1] * uv.y);
        *(float4*)(qd + 2) = make_float4(del[2] * L2E, del[2] * uv.z, del[3] * L2E, del[3] * uv.w);
    }
}

// ---------------- K6: chunked selective scan ----------------
__global__ void __launch_bounds__(128) k6_phaseA() {
    int W    = blockIdx.x * 4 + (threadIdx.x >> 5);
    int lane = threadIdx.x & 31;
    int c = W / 192;
    int p = W % 192;
    int half = lane >> 4;
    int n = lane & 15;
    int g = 2 * p + half;
    int d = g % DI;
    int b = g / DI;
    float An = g_An[d * DSN + n];
    const float2* q  = g_q2 + (size_t)g * LT;
    const float2* bc = g_bc + (size_t)b * LT * DSN;
    float h = 0.f, P = 1.f;
    int l0 = c * CL;
#pragma unroll 4
    for (int l = l0; l < l0 + CL; l++) {
        float2 qq = q[l];
        float2 bv = bc[(size_t)l * DSN + n];
        float a = ex2(qq.x * An);
        P *= a;
        h = a * h + qq.y * bv.x;
    }
    int idx = (g * NC + c) * DSN + n;
    g_hend[idx] = h;
    g_P[idx]    = P;
}

__global__ void k6_phaseB() {
    int t = blockIdx.x * blockDim.x + threadIdx.x;
    if (t >= BB * DI * DSN) return;
    int n = t & 15;
    int g = t >> 4;
    float h = 0.f;
    for (int c = 0; c < NC; c++) {
        int idx = (g * NC + c) * DSN + n;
        g_h0[idx] = h;
        h = g_P[idx] * h + g_hend[idx];
    }
}

__global__ void __launch_bounds__(128) k6_phaseC(const float* __restrict__ dsv) {
    int W    = blockIdx.x * 4 + (threadIdx.x >> 5);
    int lane = threadIdx.x & 31;
    int c = W / 192;
    int p = W % 192;
    int half = lane >> 4;
    int n = lane & 15;
    int g = 2 * p + half;
    int d = g % DI;
    int b = g / DI;
    float An = g_An[d * DSN + n];
    float ds = dsv[d];
    const float2* q  = g_q2 + (size_t)g * LT;
    const float* u   = g_xs + (size_t)g * LT;
    const float2* bc = g_bc + (size_t)b * LT * DSN;
    float h = g_h0[(g * NC + c) * DSN + n];
    int l0 = c * CL;
#pragma unroll 2
    for (int l = l0; l < l0 + CL; l++) {
        float2 qq = q[l];
        float2 bv = bc[(size_t)l * DSN + n];
        float a = ex2(qq.x * An);
        h = a * h + qq.y * bv.x;
        float pr = h * bv.y;
        pr += __shfl_xor_sync(0xffffffffu, pr, 1);
        pr += __shfl_xor_sync(0xffffffffu, pr, 2);
        pr += __shfl_xor_sync(0xffffffffu, pr, 4);
        pr += __shfl_xor_sync(0xffffffffu, pr, 8);
        if (n == 0 && l >= CC) {
            g_yt[((size_t)b * LL + (l - CC)) * DI + d] = pr + ds * u[l];
        }
    }
}

// ---------------- K7: LayerNorm + SiLU(z) gate + out_proj (8 l per block) ----------------
__global__ void __launch_bounds__(192) k7_out(const float* __restrict__ onw,
                                              const float* __restrict__ onb,
                                              float* __restrict__ out) {
    __shared__ __align__(16) float sy [8 * DI];
    __shared__ __align__(16) float sgv[8 * DI];
    __shared__ __align__(16) float sred[8 * DM];
    __shared__ float smu[8], srs[8];
    int b   = blockIdx.y;
    int l0  = blockIdx.x * 8;
    int tid = threadIdx.x;
    int lane = tid & 31, w = tid >> 5;

    const float4* ysrc = (const float4*)(g_yt + ((size_t)b * LL + l0) * DI);
    float4* syd = (float4*)sy;
#pragma unroll
    for (int i = 0; i < 2; i++) syd[tid + 192 * i] = ysrc[tid + 192 * i];
    __syncthreads();

#pragma unroll
    for (int pass = 0; pass < 2; pass++) {
        int l = pass * 6 + w;
        if (l < 8) {
            float s1 = 0.f, s2 = 0.f;
#pragma unroll
            for (int k = 0; k < 6; k++) {
                float v = sy[l * DI + lane + 32 * k];
                s1 += v; s2 += v * v;
            }
#pragma unroll
            for (int o = 16; o > 0; o >>= 1) {
                s1 += __shfl_xor_sync(0xffffffffu, s1, o);
                s2 += __shfl_xor_sync(0xffffffffu, s2, o);
            }
            if (lane == 0) {
                float mu = s1 * (1.f / 192.f);
                smu[l] = mu;
                srs[l] = rsqrtf(s2 * (1.f / 192.f) - mu * mu + 1e-5f);
            }
        }
    }
    __syncthreads();

    float wn = onw[tid], bn = onb[tid];
    const float* zr = g_z + ((size_t)b * LL + l0) * DI + tid;
#pragma unroll
    for (int l = 0; l < 8; l++) {
        float y  = sy[l * DI + tid];
        float yn = (y - smu[l]) * srs[l] * wn + bn;
        float zv = zr[(size_t)l * DI];
        sgv[l * DI + tid] = yn * silu_f(zv);
    }
    __syncthreads();

    int o = tid % DM, half = tid / DM, d0 = half * DM;
    float acc[8];
#pragma unroll
    for (int l = 0; l < 8; l++) acc[l] = 0.f;
    const float* wp = g_wtO + (size_t)d0 * DM + o;
#pragma unroll 4
    for (int i = 0; i < 96; i++) {
        float wv = wp[(size_t)i * DM];
        const float* gv = sgv + d0 + i;
#pragma unroll
        for (int l = 0; l < 8; l++) acc[l] += gv[l * DI] * wv;
    }
    if (half == 0) {
#pragma unroll
        for (int l = 0; l < 8; l++) sred[l * DM + o] = acc[l];
    }
    __syncthreads();
    if (half == 1) {
        float* op = out + ((size_t)b * LL + l0) * DM + o;
#pragma unroll
        for (int l = 0; l < 8; l++) op[(size_t)l * DM] = acc[l] + sred[l * DM + o];
    }
}

// ---------------- launch ----------------
extern "C" void kernel_launch(void* const* d_in, const int* in_sizes, int n_in,
                              void* d_out, int out_size) {
    const float* x            = (const float*)d_in[0];
    const float* in_proj_w    = (const float*)d_in[1];
    const float* conv2d_w     = (const float*)d_in[2];
    const float* conv2d_b     = (const float*)d_in[3];
    const float* depth_conv_w = (const float*)d_in[4];
    const float* depth_conv_b = (const float*)d_in[5];
    const float* depth_fc_w   = (const float*)d_in[6];
    const float* depth_fc_b   = (const float*)d_in[7];
    const float* x_proj_w     = (const float*)d_in[8];
    const float* dt_projs_w   = (const float*)d_in[9];
    const float* dt_projs_b   = (const float*)d_in[10];
    const float* A_logs       = (const float*)d_in[11];
    const float* Ds           = (const float*)d_in[12];
    const float* out_norm_w   = (const float*)d_in[13];
    const float* out_norm_b   = (const float*)d_in[14];
    const float* out_proj_w   = (const float*)d_in[15];
    float* out = (float*)d_out;

    k0_prep<<<(2 * DI * DM + 255) / 256, 256>>>(in_proj_w, out_proj_w, A_logs);
    k1_inproj<<<dim3(LL / 32, BB), 384>>>(x);
    k2_conv<<<dim3(16, BB * DI), 256>>>(conv2d_w, conv2d_b);
    k3_dconv<<<dim3(4, BB * DI), 256>>>(depth_conv_w, depth_conv_b);
    k4_fc<<<dim3(24, BB), 384>>>(depth_fc_w, depth_fc_b);
    k5_xproj<<<dim3(LT / 32, BB), 256>>>(x_proj_w, dt_projs_w, dt_projs_b, Ds);
    k6_phaseA<<<(192 * NC) / 4, 128>>>();
    k6_phaseB<<<24, 256>>>();
    k6_phaseC<<<(192 * NC) / 4, 128>>>(Ds);
    k7_out<<<dim3(LL / 8, BB), 192>>>(out_norm_w, out_norm_b, out);
}